// round 11
// baseline (speedup 1.0000x reference)
#include <cuda_runtime.h>
#include <cuda_fp16.h>
#include <stdint.h>

#define NB   4
#define HH   224
#define WW   224
#define CIN  256
#define FOUT 256
#define BCB  16
#define OBS  14
#define FT   64            // F per CTA
#define CCH  32            // channels per chunk
#define NCHUNK (CIN / CCH) // 8
#define THREADS 256

// dynamic smem: A double buffer 2*20736 ; B(3 taps) double buffer 2*12288
#define ABUF    20736
#define SMEM_B  (2 * ABUF)            // 41472
#define BBUF    12288
#define SMEM_SZ (2 * ABUF + 2 * BBUF) // 66048

__device__ float  g_active[NB * BCB * BCB];
__device__ __half g_wf16[9 * 256 * 256];   // [tap][f][c]

static __device__ __forceinline__ uint32_t s2u(const void* p) {
    uint32_t a;
    asm("{ .reg .u64 t; cvta.to.shared.u64 t, %1; cvt.u32.u64 %0, t; }"
        : "=r"(a) : "l"(p));
    return a;
}
static __device__ __forceinline__ uint32_t f2h2(float lo, float hi) {
    uint32_t r;
    asm("cvt.rn.f16x2.f32 %0, %1, %2;" : "=r"(r) : "f"(hi), "f"(lo));
    return r;
}
static __device__ __forceinline__ void ldsm4(uint32_t* r, uint32_t addr) {
    asm volatile("ldmatrix.sync.aligned.m8n8.x4.shared.b16 {%0,%1,%2,%3}, [%4];"
                 : "=r"(r[0]), "=r"(r[1]), "=r"(r[2]), "=r"(r[3]) : "r"(addr));
}
static __device__ __forceinline__ void mma16816(float* d, const uint32_t* a,
                                                uint32_t b0, uint32_t b1) {
    asm volatile(
        "mma.sync.aligned.m16n8k16.row.col.f32.f16.f16.f32 "
        "{%0,%1,%2,%3}, {%4,%5,%6,%7}, {%8,%9}, {%0,%1,%2,%3};"
        : "+f"(d[0]), "+f"(d[1]), "+f"(d[2]), "+f"(d[3])
        : "r"(a[0]), "r"(a[1]), "r"(a[2]), "r"(a[3]), "r"(b0), "r"(b1));
}
static __device__ __forceinline__ void cpasync16(uint32_t saddr, const void* gptr) {
    asm volatile("cp.async.cg.shared.global [%0], [%1], 16;"
                 :: "r"(saddr), "l"(gptr));
}

// ---------------------------------------------------------------------------
// Kernel 0 (fused prep): blocks 0..2303 convert weights; 2304..2307 gates
// ---------------------------------------------------------------------------
__global__ void prep_kernel(const float* __restrict__ ker,
                            const float* __restrict__ mask) {
    int b = blockIdx.x, tid = threadIdx.x;
    if (b < 2304) {
        int idx = b * 256 + tid;
        int c = idx & 255, f = (idx >> 8) & 255, tap = idx >> 16;
        g_wf16[idx] = __float2half_rn(ker[(tap * 256 + c) * 256 + f]);
    } else {
        int idx = (b - 2304) * 256 + tid;      // 0..1023
        int bj = idx & 15, bi = (idx >> 4) & 15, n = idx >> 8;
        int y0 = bi * OBS - 1, x0 = bj * OBS - 1;
        float s = 0.0f;
        for (int i = 0; i < 16; ++i) {
            int y = y0 + i;
            if ((unsigned)y >= (unsigned)HH) continue;
            const float* row = mask + (n * HH + y) * WW;
            for (int j = 0; j < 16; ++j) {
                int x = x0 + j;
                if ((unsigned)x < (unsigned)WW) s += row[x];
            }
        }
        g_active[idx] = (s * (1.0f / 256.0f) > 0.5f) ? 1.0f : 0.0f;
    }
}

// ---------------------------------------------------------------------------
// Kernel 1: HMMA implicit-GEMM conv. Grid (4 fg, 256 blocks, 4 images).
// 8 warps; warp owns 32 px rows (M=256 total), N=64, K=2304.
// 24 groups (8 c-chunks x 3 dx); 3 dy-taps share A frags per group.
// B staged via cp.async; B fragments double-buffered through the MMA chain.
// ---------------------------------------------------------------------------
__global__ void __launch_bounds__(THREADS, 2)
conv_mma(const float* __restrict__ in, const float* __restrict__ bias,
         float* __restrict__ out) {
    extern __shared__ char smem[];
    const uint32_t sA = s2u(smem);
    const uint32_t sB = sA + SMEM_B;

    const int tid = threadIdx.x, wid = tid >> 5, lane = tid & 31;
    const int fg = blockIdx.x;
    const int bi = blockIdx.y >> 4, bj = blockIdx.y & 15;
    const int n = blockIdx.z;
    const int f0 = fg * FT;

    const float act = g_active[n * 256 + blockIdx.y];
    if (act == 0.0f) {
        float4 z = make_float4(0.f, 0.f, 0.f, 0.f);
        for (int idx = tid; idx < 196 * 16; idx += THREADS) {
            int q = idx & 15, p = idx >> 4;
            int hh = bi * OBS + p / OBS, wc = bj * OBS + p % OBS;
            *(float4*)&out[(((size_t)n * HH + hh) * WW + wc) * FOUT + f0 + q * 4] = z;
        }
        return;
    }

    const int ybase = bi * OBS - 1, xbase = bj * OBS - 1;

    float acc[2][8][4];
#pragma unroll
    for (int a = 0; a < 2; ++a)
#pragma unroll
        for (int b = 0; b < 8; ++b)
#pragma unroll
            for (int c = 0; c < 4; ++c) acc[a][b][c] = 0.0f;

    // ---- full A staging (prologue): 324 px x 32c f16, swizzled ----
    auto stageA = [&](int c0, int abuf) {
#pragma unroll
        for (int it = 0; it < 6; ++it) {
            int i = tid + it * THREADS;
            if (i >= 324 * 4) break;
            int p = i >> 2, j = i & 3;
            int y = ybase + p / 18, x = xbase + p % 18;
            float4 v0 = make_float4(0.f, 0.f, 0.f, 0.f), v1 = v0;
            if ((unsigned)y < (unsigned)HH && (unsigned)x < (unsigned)WW) {
                const float* gp = in + ((((size_t)n * HH + y) * WW + x) << 8) + c0 + j * 8;
                v0 = *(const float4*)gp;
                v1 = *(const float4*)(gp + 4);
            }
            int jp = (j + (p >> 1)) & 3;
            *(uint4*)(smem + abuf * ABUF + p * 64 + 16 * jp) =
                make_uint4(f2h2(v0.x, v0.y), f2h2(v0.z, v0.w),
                           f2h2(v1.x, v1.y), f2h2(v1.z, v1.w));
        }
    };

    // ---- B staging via cp.async: 3 taps x [64 f][32 c] per group ----
    const int bf = tid >> 2, bjj = tid & 3;
    const int bjp = (bjj + ((bf >> 1) & 3)) & 3;
    auto issueB3 = [&](int kcn, int dxn, int buf) {
#pragma unroll
        for (int dy = 0; dy < 3; ++dy) {
            int tap = dy * 3 + dxn;
            cpasync16(sB + buf * BBUF + dy * 4096 + bf * 64 + 16 * bjp,
                      g_wf16 + ((size_t)(tap * 256 + f0 + bf) << 8) + kcn * CCH + bjj * 8);
        }
        asm volatile("cp.async.commit_group;");
    };

    // prologue
    issueB3(0, 0, 0);
    stageA(0, 0);
    asm volatile("cp.async.wait_group 0;");
    __syncthreads();

    const bool hasItemB = (tid < 176);
    int dx = 0, kc = 0;
    for (int G = 0; G < 24; ++G) {
        const bool hasNext = (G < 23);
        if (hasNext) {
            int dxn = dx + 1, kcn = kc;
            if (dxn == 3) { dxn = 0; ++kcn; }
            issueB3(kcn, dxn, (G + 1) & 1);
        }
        // ---- next-chunk A slice LDGs (1296 items over the 3 groups) ----
        const bool doSlice = (kc < NCHUNK - 1);
        float4 va0, va1, vb0, vb1;
        int spA = 0, sjA = 0, spB = 0, sjB = 0;
        if (doSlice) {
            int i = dx * 432 + tid;
            spA = i >> 2; sjA = i & 3;
            int y = ybase + spA / 18, x = xbase + spA % 18;
            va0 = make_float4(0.f, 0.f, 0.f, 0.f); va1 = va0;
            if ((unsigned)y < (unsigned)HH && (unsigned)x < (unsigned)WW) {
                const float* gp = in + ((((size_t)n * HH + y) * WW + x) << 8) +
                                  (kc + 1) * CCH + sjA * 8;
                va0 = *(const float4*)gp; va1 = *(const float4*)(gp + 4);
            }
            if (hasItemB) {
                int i2 = dx * 432 + 256 + tid;
                spB = i2 >> 2; sjB = i2 & 3;
                int y2 = ybase + spB / 18, x2 = xbase + spB % 18;
                vb0 = make_float4(0.f, 0.f, 0.f, 0.f); vb1 = vb0;
                if ((unsigned)y2 < (unsigned)HH && (unsigned)x2 < (unsigned)WW) {
                    const float* gp = in + ((((size_t)n * HH + y2) * WW + x2) << 8) +
                                      (kc + 1) * CCH + sjB * 8;
                    vb0 = *(const float4*)gp; vb1 = *(const float4*)(gp + 4);
                }
            }
        }

        const uint32_t aB = sA + (uint32_t)(kc & 1) * ABUF;
        const uint32_t bbuf = sB + (uint32_t)(G & 1) * BBUF;
#pragma unroll
        for (int ks = 0; ks < 2; ++ks) {
            const int j0 = ks * 2 + (lane >> 4);
            uint32_t afr[4][4];
#pragma unroll
            for (int pg = 0; pg < 4; ++pg) {
                int p = (wid * 2 + pg) * 18 + (lane & 15) + dx;
                uint32_t rowa = aB + p * 64;
                int psw = (p >> 1) & 3;
                ldsm4(afr[pg], rowa + 16 * ((j0 + psw) & 3));
            }
            // B fragment address for (dy, ng)
            const int fb = (lane & 7) + ((lane >> 3) & 1) * 8;
            auto baddr = [&](int dy, int ng) {
                int f = ng * 16 + fb;
                int fsw = (f >> 1) & 3;
                return bbuf + dy * 4096 + f * 64 + 16 * ((j0 + fsw) & 3);
            };
            // pipelined chain over 12 (dy, ng) fragments
            uint32_t bfr[2][4];
            ldsm4(bfr[0], baddr(0, 0));
#pragma unroll
            for (int t = 0; t < 12; ++t) {
                const int dy = t >> 2, ng = t & 3;
                if (t + 1 < 12)
                    ldsm4(bfr[(t + 1) & 1], baddr((t + 1) >> 2, (t + 1) & 3));
                const uint32_t* bc = bfr[t & 1];
#pragma unroll
                for (int mt = 0; mt < 2; ++mt)
#pragma unroll
                    for (int nh = 0; nh < 2; ++nh)
                        mma16816(acc[mt][ng * 2 + nh], afr[mt + dy],
                                 bc[nh], bc[nh + 2]);
            }
        }

        // ---- land A slices, drain B cp.async, publish ----
        if (doSlice) {
            int jp = (sjA + (spA >> 1)) & 3;
            *(uint4*)(smem + ((kc + 1) & 1) * ABUF + spA * 64 + 16 * jp) =
                make_uint4(f2h2(va0.x, va0.y), f2h2(va0.z, va0.w),
                           f2h2(va1.x, va1.y), f2h2(va1.z, va1.w));
            if (hasItemB) {
                int jp2 = (sjB + (spB >> 1)) & 3;
                *(uint4*)(smem + ((kc + 1) & 1) * ABUF + spB * 64 + 16 * jp2) =
                    make_uint4(f2h2(vb0.x, vb0.y), f2h2(vb0.z, vb0.w),
                               f2h2(vb1.x, vb1.y), f2h2(vb1.z, vb1.w));
            }
        }
        asm volatile("cp.async.wait_group 0;");
        __syncthreads();

        if (++dx == 3) { dx = 0; ++kc; }
    }

    // ---- epilogue: bias + relu + store ----
    const int warpM = wid * 32;
    float2 b2[8];
#pragma unroll
    for (int ng = 0; ng < 8; ++ng)
        b2[ng] = *(const float2*)&bias[f0 + ng * 8 + (lane & 3) * 2];

#pragma unroll
    for (int mt = 0; mt < 2; ++mt)
#pragma unroll
        for (int rr = 0; rr < 2; ++rr) {
            int m = warpM + mt * 16 + rr * 8 + (lane >> 2);
            int oy = m >> 4, ox = m & 15;
            if (oy >= OBS || ox >= OBS) continue;
            float* op = out + ((((size_t)n * HH + bi * OBS + oy) * WW) +
                               bj * OBS + ox) * FOUT + f0 + (lane & 3) * 2;
#pragma unroll
            for (int ng = 0; ng < 8; ++ng) {
                float2 v;
                v.x = fmaxf(acc[mt][ng][rr * 2 + 0] + b2[ng].x, 0.f);
                v.y = fmaxf(acc[mt][ng][rr * 2 + 1] + b2[ng].y, 0.f);
                *(float2*)(op + ng * 8) = v;
            }
        }
}

// ---------------------------------------------------------------------------
extern "C" void kernel_launch(void* const* d_in, const int* in_sizes, int n_in,
                              void* d_out, int out_size) {
    const float* inputs = (const float*)d_in[0];   // (4,224,224,256)
    const float* mask   = (const float*)d_in[1];   // (4,224,224,1)
    const float* kernel = (const float*)d_in[2];   // (3,3,256,256)
    const float* bias   = (const float*)d_in[3];   // (256,)
    float* out = (float*)d_out;

    static int configured = 0;
    if (!configured) {
        cudaFuncSetAttribute(conv_mma, cudaFuncAttributeMaxDynamicSharedMemorySize,
                             SMEM_SZ);
        configured = 1;
    }

    prep_kernel<<<2308, 256>>>(kernel, mask);

    dim3 grid(FOUT / FT, BCB * BCB, NB);           // (4, 256, 4)
    conv_mma<<<grid, THREADS, SMEM_SZ>>>(inputs, bias, out);
}

// round 14
// speedup vs baseline: 1.0179x; 1.0179x over previous
#include <cuda_runtime.h>
#include <cuda_fp16.h>
#include <stdint.h>

#define NB   4
#define HH   224
#define WW   224
#define CIN  256
#define FOUT 256
#define BCB  16
#define OBS  14
#define FT   64            // F per CTA
#define CCH  32            // channels per chunk
#define NCHUNK (CIN / CCH) // 8
#define THREADS 256
#define MWARPS 7           // warps issuing MMAs (M = 224 real rows)

// dynamic smem: A double buffer 2*20736 ; B(3 taps) double buffer 2*12288
#define ABUF    20736
#define SMEM_B  (2 * ABUF)            // 41472
#define BBUF    12288
#define SMEM_SZ (2 * ABUF + 2 * BBUF) // 66048

__device__ float  g_active[NB * BCB * BCB];
__device__ __half g_wf16[9 * 256 * 256];   // [tap][f][c]

static __device__ __forceinline__ uint32_t s2u(const void* p) {
    uint32_t a;
    asm("{ .reg .u64 t; cvta.to.shared.u64 t, %1; cvt.u32.u64 %0, t; }"
        : "=r"(a) : "l"(p));
    return a;
}
static __device__ __forceinline__ uint32_t f2h2(float lo, float hi) {
    uint32_t r;
    asm("cvt.rn.f16x2.f32 %0, %1, %2;" : "=r"(r) : "f"(hi), "f"(lo));
    return r;
}
static __device__ __forceinline__ void ldsm4(uint32_t* r, uint32_t addr) {
    asm volatile("ldmatrix.sync.aligned.m8n8.x4.shared.b16 {%0,%1,%2,%3}, [%4];"
                 : "=r"(r[0]), "=r"(r[1]), "=r"(r[2]), "=r"(r[3]) : "r"(addr));
}
static __device__ __forceinline__ void mma16816(float* d, const uint32_t* a,
                                                uint32_t b0, uint32_t b1) {
    asm volatile(
        "mma.sync.aligned.m16n8k16.row.col.f32.f16.f16.f32 "
        "{%0,%1,%2,%3}, {%4,%5,%6,%7}, {%8,%9}, {%0,%1,%2,%3};"
        : "+f"(d[0]), "+f"(d[1]), "+f"(d[2]), "+f"(d[3])
        : "r"(a[0]), "r"(a[1]), "r"(a[2]), "r"(a[3]), "r"(b0), "r"(b1));
}
static __device__ __forceinline__ void cpasync16(uint32_t saddr, const void* gptr) {
    asm volatile("cp.async.cg.shared.global [%0], [%1], 16;"
                 :: "r"(saddr), "l"(gptr));
}

// ---------------------------------------------------------------------------
// Kernel 0 (fused prep): blocks 0..2303 convert weights; 2304..2307 gates
// ---------------------------------------------------------------------------
__global__ void prep_kernel(const float* __restrict__ ker,
                            const float* __restrict__ mask) {
    int b = blockIdx.x, tid = threadIdx.x;
    if (b < 2304) {
        int idx = b * 256 + tid;
        int c = idx & 255, f = (idx >> 8) & 255, tap = idx >> 16;
        g_wf16[idx] = __float2half_rn(ker[(tap * 256 + c) * 256 + f]);
    } else {
        int idx = (b - 2304) * 256 + tid;      // 0..1023
        int bj = idx & 15, bi = (idx >> 4) & 15, n = idx >> 8;
        int y0 = bi * OBS - 1, x0 = bj * OBS - 1;
        float s = 0.0f;
        for (int i = 0; i < 16; ++i) {
            int y = y0 + i;
            if ((unsigned)y >= (unsigned)HH) continue;
            const float* row = mask + (n * HH + y) * WW;
            for (int j = 0; j < 16; ++j) {
                int x = x0 + j;
                if ((unsigned)x < (unsigned)WW) s += row[x];
            }
        }
        g_active[idx] = (s * (1.0f / 256.0f) > 0.5f) ? 1.0f : 0.0f;
    }
}

// ---------------------------------------------------------------------------
// Kernel 1: HMMA implicit-GEMM conv. Grid (4 fg, 256 blocks, 4 images).
// M=224 real pixel rows: warps 0..6 compute M32xN64 tiles; warp 7 only stages.
// 24 groups (8 c-chunks x 3 dx); 3 dy-taps share A frags per group.
// ---------------------------------------------------------------------------
__global__ void __launch_bounds__(THREADS, 2)
conv_mma(const float* __restrict__ in, const float* __restrict__ bias,
         float* __restrict__ out) {
    extern __shared__ char smem[];
    const uint32_t sA = s2u(smem);
    const uint32_t sB = sA + SMEM_B;

    const int tid = threadIdx.x, wid = tid >> 5, lane = tid & 31;
    const int fg = blockIdx.x;
    const int bi = blockIdx.y >> 4, bj = blockIdx.y & 15;
    const int n = blockIdx.z;
    const int f0 = fg * FT;

    const float act = g_active[n * 256 + blockIdx.y];
    if (act == 0.0f) {
        float4 z = make_float4(0.f, 0.f, 0.f, 0.f);
        for (int idx = tid; idx < 196 * 16; idx += THREADS) {
            int q = idx & 15, p = idx >> 4;
            int hh = bi * OBS + p / OBS, wc = bj * OBS + p % OBS;
            *(float4*)&out[(((size_t)n * HH + hh) * WW + wc) * FOUT + f0 + q * 4] = z;
        }
        return;
    }

    const int ybase = bi * OBS - 1, xbase = bj * OBS - 1;

    float acc[2][8][4];
#pragma unroll
    for (int a = 0; a < 2; ++a)
#pragma unroll
        for (int b = 0; b < 8; ++b)
#pragma unroll
            for (int c = 0; c < 4; ++c) acc[a][b][c] = 0.0f;

    // ---- full A staging (prologue): 324 px x 32c f16, swizzled ----
    auto stageA = [&](int c0, int abuf) {
#pragma unroll
        for (int it = 0; it < 6; ++it) {
            int i = tid + it * THREADS;
            if (i >= 324 * 4) break;
            int p = i >> 2, j = i & 3;
            int y = ybase + p / 18, x = xbase + p % 18;
            float4 v0 = make_float4(0.f, 0.f, 0.f, 0.f), v1 = v0;
            if ((unsigned)y < (unsigned)HH && (unsigned)x < (unsigned)WW) {
                const float* gp = in + ((((size_t)n * HH + y) * WW + x) << 8) + c0 + j * 8;
                v0 = *(const float4*)gp;
                v1 = *(const float4*)(gp + 4);
            }
            int jp = (j + (p >> 1)) & 3;
            *(uint4*)(smem + abuf * ABUF + p * 64 + 16 * jp) =
                make_uint4(f2h2(v0.x, v0.y), f2h2(v0.z, v0.w),
                           f2h2(v1.x, v1.y), f2h2(v1.z, v1.w));
        }
    };

    // ---- B staging via cp.async: 3 taps x [64 f][32 c] per group ----
    const int bf = tid >> 2, bjj = tid & 3;
    const int bjp = (bjj + ((bf >> 1) & 3)) & 3;
    auto issueB3 = [&](int kcn, int dxn, int buf) {
#pragma unroll
        for (int dy = 0; dy < 3; ++dy) {
            int tap = dy * 3 + dxn;
            cpasync16(sB + buf * BBUF + dy * 4096 + bf * 64 + 16 * bjp,
                      g_wf16 + ((size_t)(tap * 256 + f0 + bf) << 8) + kcn * CCH + bjj * 8);
        }
        asm volatile("cp.async.commit_group;");
    };

    // prologue
    issueB3(0, 0, 0);
    stageA(0, 0);
    asm volatile("cp.async.wait_group 0;");
    __syncthreads();

    const bool hasItemB = (tid < 176);
    int dx = 0, kc = 0;
    for (int G = 0; G < 24; ++G) {
        const bool hasNext = (G < 23);
        if (hasNext) {
            int dxn = dx + 1, kcn = kc;
            if (dxn == 3) { dxn = 0; ++kcn; }
            issueB3(kcn, dxn, (G + 1) & 1);
        }
        // ---- next-chunk A slice LDGs (1296 items over the 3 groups) ----
        const bool doSlice = (kc < NCHUNK - 1);
        float4 va0, va1, vb0, vb1;
        int spA = 0, sjA = 0, spB = 0, sjB = 0;
        if (doSlice) {
            int i = dx * 432 + tid;
            spA = i >> 2; sjA = i & 3;
            int y = ybase + spA / 18, x = xbase + spA % 18;
            va0 = make_float4(0.f, 0.f, 0.f, 0.f); va1 = va0;
            if ((unsigned)y < (unsigned)HH && (unsigned)x < (unsigned)WW) {
                const float* gp = in + ((((size_t)n * HH + y) * WW + x) << 8) +
                                  (kc + 1) * CCH + sjA * 8;
                va0 = *(const float4*)gp; va1 = *(const float4*)(gp + 4);
            }
            if (hasItemB) {
                int i2 = dx * 432 + 256 + tid;
                spB = i2 >> 2; sjB = i2 & 3;
                int y2 = ybase + spB / 18, x2 = xbase + spB % 18;
                vb0 = make_float4(0.f, 0.f, 0.f, 0.f); vb1 = vb0;
                if ((unsigned)y2 < (unsigned)HH && (unsigned)x2 < (unsigned)WW) {
                    const float* gp = in + ((((size_t)n * HH + y2) * WW + x2) << 8) +
                                      (kc + 1) * CCH + sjB * 8;
                    vb0 = *(const float4*)gp; vb1 = *(const float4*)(gp + 4);
                }
            }
        }

        // ---- MMA block: warps 0..6 only (M rows 0..223 are real) ----
        if (wid < MWARPS) {
            const uint32_t aB = sA + (uint32_t)(kc & 1) * ABUF;
            const uint32_t bbuf = sB + (uint32_t)(G & 1) * BBUF;
#pragma unroll
            for (int ks = 0; ks < 2; ++ks) {
                const int j0 = ks * 2 + (lane >> 4);
                uint32_t afr[4][4];
#pragma unroll
                for (int pg = 0; pg < 4; ++pg) {
                    int p = (wid * 2 + pg) * 18 + (lane & 15) + dx;
                    uint32_t rowa = aB + p * 64;
                    int psw = (p >> 1) & 3;
                    ldsm4(afr[pg], rowa + 16 * ((j0 + psw) & 3));
                }
                const int fb = (lane & 7) + ((lane >> 3) & 1) * 8;
                auto baddr = [&](int dy, int ng) {
                    int f = ng * 16 + fb;
                    int fsw = (f >> 1) & 3;
                    return bbuf + dy * 4096 + f * 64 + 16 * ((j0 + fsw) & 3);
                };
                uint32_t bfr[2][4];
                ldsm4(bfr[0], baddr(0, 0));
#pragma unroll
                for (int t = 0; t < 12; ++t) {
                    const int dy = t >> 2, ng = t & 3;
                    if (t + 1 < 12)
                        ldsm4(bfr[(t + 1) & 1], baddr((t + 1) >> 2, (t + 1) & 3));
                    const uint32_t* bc = bfr[t & 1];
#pragma unroll
                    for (int mt = 0; mt < 2; ++mt)
#pragma unroll
                        for (int nh = 0; nh < 2; ++nh)
                            mma16816(acc[mt][ng * 2 + nh], afr[mt + dy],
                                     bc[nh], bc[nh + 2]);
                }
            }
        }

        // ---- land A slices, drain B cp.async, publish ----
        if (doSlice) {
            int jp = (sjA + (spA >> 1)) & 3;
            *(uint4*)(smem + ((kc + 1) & 1) * ABUF + spA * 64 + 16 * jp) =
                make_uint4(f2h2(va0.x, va0.y), f2h2(va0.z, va0.w),
                           f2h2(va1.x, va1.y), f2h2(va1.z, va1.w));
            if (hasItemB) {
                int jp2 = (sjB + (spB >> 1)) & 3;
                *(uint4*)(smem + ((kc + 1) & 1) * ABUF + spB * 64 + 16 * jp2) =
                    make_uint4(f2h2(vb0.x, vb0.y), f2h2(vb0.z, vb0.w),
                               f2h2(vb1.x, vb1.y), f2h2(vb1.z, vb1.w));
            }
        }
        asm volatile("cp.async.wait_group 0;");
        __syncthreads();

        if (++dx == 3) { dx = 0; ++kc; }
    }

    // ---- epilogue: bias + relu + store (warps 0..6) ----
    if (wid < MWARPS) {
        const int warpM = wid * 32;
        float2 b2[8];
#pragma unroll
        for (int ng = 0; ng < 8; ++ng)
            b2[ng] = *(const float2*)&bias[f0 + ng * 8 + (lane & 3) * 2];

#pragma unroll
        for (int mt = 0; mt < 2; ++mt)
#pragma unroll
            for (int rr = 0; rr < 2; ++rr) {
                int m = warpM + mt * 16 + rr * 8 + (lane >> 2);
                int oy = m >> 4, ox = m & 15;
                if (ox >= OBS) continue;        // oy <= 13 always for wid < 7
                float* op = out + ((((size_t)n * HH + bi * OBS + oy) * WW) +
                                   bj * OBS + ox) * FOUT + f0 + (lane & 3) * 2;
#pragma unroll
                for (int ng = 0; ng < 8; ++ng) {
                    float2 v;
                    v.x = fmaxf(acc[mt][ng][rr * 2 + 0] + b2[ng].x, 0.f);
                    v.y = fmaxf(acc[mt][ng][rr * 2 + 1] + b2[ng].y, 0.f);
                    *(float2*)(op + ng * 8) = v;
                }
            }
    }
}

// ---------------------------------------------------------------------------
extern "C" void kernel_launch(void* const* d_in, const int* in_sizes, int n_in,
                              void* d_out, int out_size) {
    const float* inputs = (const float*)d_in[0];   // (4,224,224,256)
    const float* mask   = (const float*)d_in[1];   // (4,224,224,1)
    const float* kernel = (const float*)d_in[2];   // (3,3,256,256)
    const float* bias   = (const float*)d_in[3];   // (256,)
    float* out = (float*)d_out;

    static int configured = 0;
    if (!configured) {
        cudaFuncSetAttribute(conv_mma, cudaFuncAttributeMaxDynamicSharedMemorySize,
                             SMEM_SZ);
        configured = 1;
    }

    prep_kernel<<<2308, 256>>>(kernel, mask);

    dim3 grid(FOUT / FT, BCB * BCB, NB);           // (4, 256, 4)
    conv_mma<<<grid, THREADS, SMEM_SZ>>>(inputs, bias, out);
}